// round 15
// baseline (speedup 1.0000x reference)
#include <cuda_runtime.h>
#include <cuda_bf16.h>
#include <mma.h>
#include <math.h>
#include <cstdint>

using namespace nvcuda;

#define NN    50000
#define NPAD  50048          // 391 * 128
#define EE    800000

// ---------------- scratch (device globals; no allocation) ----------------
__device__ float g_TMP[(size_t)NPAD * 128];    // embed-product temp
__device__ float g_AGG[(size_t)NPAD * 256];    // [target_x (S@W_tg) | target_y (aggx@W_tg)]
__device__ float g_P1[(size_t)NPAD * 256];     // [h1x | h1y]
__device__ float g_Won1[128 * 128];            // W_on @ W1
__device__ int   g_deg[NN];
__device__ int   g_off[NN + 8];
__device__ int   g_cur[NN];
__device__ int   g_btot[64];
__device__ int   g_scol[EE];
__device__ float g_sw[EE];
__device__ float g_bnsum[512];                 // [sum(256) | sumsq(256)]
__device__ float g_bnaff[512];                 // [scale(256) | shift(256)]
__device__ float g_c1[128];                    // b_on @ W1 + b1
__device__ float g_loss;

// ---------------- init ----------------
__global__ void k_zero() {
    int i = blockIdx.x * 256 + threadIdx.x;
    if (i < NN)  g_deg[i] = 0;
    if (i < 512) g_bnsum[i] = 0.f;
    if (i == 0)  g_loss = 0.f;
}
__global__ void k_hist(const int* __restrict__ row) {
    int e = blockIdx.x * 256 + threadIdx.x;
    if (e < EE) atomicAdd(&g_deg[row[e]], 1);
}

// ---------------- 3-pass scan ----------------
__global__ __launch_bounds__(1024) void k_scan1() {
    __shared__ int wsum[32];
    int t = threadIdx.x, lane = t & 31, wid = t >> 5;
    int idx = blockIdx.x * 1024 + t;
    int v = (idx < NN) ? g_deg[idx] : 0;
    int incl = v;
    #pragma unroll
    for (int s = 1; s < 32; s <<= 1) {
        int a = __shfl_up_sync(0xFFFFFFFFu, incl, s);
        if (lane >= s) incl += a;
    }
    if (lane == 31) wsum[wid] = incl;
    __syncthreads();
    if (wid == 0) {
        int wv = wsum[lane];
        #pragma unroll
        for (int s = 1; s < 32; s <<= 1) {
            int a = __shfl_up_sync(0xFFFFFFFFu, wv, s);
            if (lane >= s) wv += a;
        }
        wsum[lane] = wv;
    }
    __syncthreads();
    int excl = (wid > 0 ? wsum[wid - 1] : 0) + incl - v;
    if (idx < NN) g_off[idx] = excl;
    if (t == 0) g_btot[blockIdx.x] = wsum[31];
}
__global__ void k_scan2() {
    if (threadIdx.x == 0) {
        int run = 0;
        for (int i = 0; i < 49; i++) { int v = g_btot[i]; g_btot[i] = run; run += v; }
        g_off[NN] = run;
    }
}
__global__ __launch_bounds__(1024) void k_scan3() {
    int idx = blockIdx.x * 1024 + threadIdx.x;
    if (idx < NN) {
        int o = g_off[idx] + g_btot[blockIdx.x];
        g_off[idx] = o;
        g_cur[idx] = o;
    }
}
__global__ void k_scatter(const int* __restrict__ row, const int* __restrict__ col,
                          const float* __restrict__ w) {
    int e = blockIdx.x * 256 + threadIdx.x;
    if (e < EE) {
        int r = row[e];
        int p = atomicAdd(&g_cur[r], 1);
        g_scol[p] = col[e];
        g_sw[p]   = w[e];
    }
}

// ---------------- small precomputes ----------------
__global__ void k_c1(const float* __restrict__ b_on, const float* __restrict__ W1,
                     const float* __restrict__ b1) {
    int n = threadIdx.x;
    float s = b1[n];
    for (int k = 0; k < 128; k++) s += b_on[k] * W1[k * 128 + n];
    g_c1[n] = s;
}
// W_on1 = W_on @ W1  (fp32, exact-ish)
__global__ __launch_bounds__(256) void k_won1(const float* __restrict__ W_on,
                                              const float* __restrict__ W1) {
    int idx = blockIdx.x * 256 + threadIdx.x;   // 64 blocks x 256 = 16384
    int k = idx >> 7, n = idx & 127;
    float s = 0.f;
    for (int j = 0; j < 128; j++) s += W_on[k * 128 + j] * W1[j * 128 + n];
    g_Won1[idx] = s;
}

// ---------------- bf16 hi/lo split wmma GEMM (128x128 tile, 512 thr, 16 warps) ----------------
typedef wmma::fragment<wmma::matrix_a, 16, 16, 16, __nv_bfloat16, wmma::row_major> FragA;
typedef wmma::fragment<wmma::matrix_b, 16, 16, 16, __nv_bfloat16, wmma::row_major> FragB;
typedef wmma::fragment<wmma::accumulator, 16, 16, 16, float> FragC;

#define BLD 136                         // bf16 image leading dim (elements)
#define SLD 132                         // fp32 scratch leading dim
#define TILE (128 * BLD)                // elements per image (17408)
#define SM_AXH 0
#define SM_AXL (1 * TILE)
#define SM_AYH (2 * TILE)
#define SM_AYL (3 * TILE)
#define SM_BH  (4 * TILE)
#define SM_BL  (5 * TILE)
#define DYN_SMEM (6 * TILE * 2)         // 208896 bytes

__device__ __forceinline__ void split_store(__nv_bfloat16* sm, int hioff, int looff,
                                            int pos, float v) {
    __nv_bfloat16 h = __float2bfloat16(v);
    sm[hioff + pos] = h;
    sm[looff + pos] = __float2bfloat16(v - __bfloat162float(h));
}
__device__ __forceinline__ void stage_B(__nv_bfloat16* sm, const float* __restrict__ W, int t) {
    #pragma unroll
    for (int i = 0; i < 32; i++) {
        int idx = t + i * 512;
        int r = idx >> 7, c = idx & 127;
        split_store(sm, SM_BH, SM_BL, r * BLD + c, W[idx]);
    }
}
__device__ __forceinline__ void mm_block(const __nv_bfloat16* sm, int a_hi, FragC acc[2][2],
                                         int wid) {
    int wm = wid >> 2, wn = wid & 3;
    const __nv_bfloat16* AH = sm + a_hi + wm * 32 * BLD;
    const __nv_bfloat16* AL = AH + TILE;
    const __nv_bfloat16* BH = sm + SM_BH + wn * 32;
    const __nv_bfloat16* BL = sm + SM_BL + wn * 32;
    #pragma unroll
    for (int m = 0; m < 2; m++)
        #pragma unroll
        for (int ct = 0; ct < 2; ct++) wmma::fill_fragment(acc[m][ct], 0.f);
    #pragma unroll 1
    for (int ks = 0; ks < 8; ks++) {
        FragA ah[2], al[2];
        #pragma unroll
        for (int m = 0; m < 2; m++) {
            wmma::load_matrix_sync(ah[m], AH + m * 16 * BLD + ks * 16, BLD);
            wmma::load_matrix_sync(al[m], AL + m * 16 * BLD + ks * 16, BLD);
        }
        #pragma unroll
        for (int ct = 0; ct < 2; ct++) {
            FragB bh, bl;
            wmma::load_matrix_sync(bh, BH + ks * 16 * BLD + ct * 16, BLD);
            wmma::load_matrix_sync(bl, BL + ks * 16 * BLD + ct * 16, BLD);
            #pragma unroll
            for (int m = 0; m < 2; m++) {
                wmma::mma_sync(acc[m][ct], ah[m], bh, acc[m][ct]);
                wmma::mma_sync(acc[m][ct], ah[m], bl, acc[m][ct]);
                wmma::mma_sync(acc[m][ct], al[m], bh, acc[m][ct]);
            }
        }
    }
}
__device__ __forceinline__ void store_prod_g(FragC acc[2][2], float* outb, int ld, int wid) {
    int wm = wid >> 2, wn = wid & 3;
    #pragma unroll
    for (int m = 0; m < 2; m++)
        #pragma unroll
        for (int ct = 0; ct < 2; ct++)
            wmma::store_matrix_sync(outb + (size_t)(wm * 32 + m * 16) * ld + wn * 32 + ct * 16,
                                    acc[m][ct], ld, wmma::mem_row_major);
}
__device__ __forceinline__ void store_prod_s(FragC acc[2][2], float* fs, int wid) {
    int wm = wid >> 2, wn = wid & 3;
    #pragma unroll
    for (int m = 0; m < 2; m++)
        #pragma unroll
        for (int ct = 0; ct < 2; ct++)
            wmma::store_matrix_sync(fs + (wm * 32 + m * 16) * SLD + wn * 32 + ct * 16,
                                    acc[m][ct], SLD, wmma::mem_row_major);
}

// ---------------- MEGA: gather + 5 products + embed + P1 + BN stats ----------------
__global__ __launch_bounds__(512, 1) void k_mega(const float* __restrict__ x,
                                                 const float* __restrict__ perb,
                                                 const float* __restrict__ b_on,
                                                 const float* __restrict__ W_on,
                                                 const float* __restrict__ W_tg,
                                                 float* __restrict__ out) {
    extern __shared__ __nv_bfloat16 sm[];
    float* fs0 = (float*)sm;                          // overlays AX images (phase P1)
    float* fs1 = (float*)((char*)sm + SM_AYH * 2);    // overlays AY images
    int t = threadIdx.x, wid = t >> 5, lane = t & 31;
    int row0 = blockIdx.x * 128;

    // ---- phase 1: gather aggx and S = aggx+aggp straight into A images ----
    const float4* x4 = (const float4*)x;
    const float4* p4 = (const float4*)perb;
    #pragma unroll 1
    for (int jj = 0; jj < 8; jj++) {
        int lr = wid * 8 + jj;                 // 0..127
        int gr = row0 + lr;
        float4 ax = make_float4(0.f, 0.f, 0.f, 0.f);
        float4 ap = make_float4(0.f, 0.f, 0.f, 0.f);
        if (gr < NN) {
            int s = g_off[gr], e = g_off[gr + 1];
            int i = s;
            for (; i + 2 <= e; i += 2) {
                int c0 = g_scol[i], c1 = g_scol[i + 1];
                float w0 = g_sw[i], w1 = g_sw[i + 1];
                float4 xv0 = x4[(size_t)c0 * 32 + lane];
                float4 pv0 = p4[(size_t)c0 * 32 + lane];
                float4 xv1 = x4[(size_t)c1 * 32 + lane];
                float4 pv1 = p4[(size_t)c1 * 32 + lane];
                ax.x += w0 * xv0.x + w1 * xv1.x; ax.y += w0 * xv0.y + w1 * xv1.y;
                ax.z += w0 * xv0.z + w1 * xv1.z; ax.w += w0 * xv0.w + w1 * xv1.w;
                ap.x += w0 * pv0.x + w1 * pv1.x; ap.y += w0 * pv0.y + w1 * pv1.y;
                ap.z += w0 * pv0.z + w1 * pv1.z; ap.w += w0 * pv0.w + w1 * pv1.w;
            }
            for (; i < e; i++) {
                int c = g_scol[i]; float w = g_sw[i];
                float4 xv = x4[(size_t)c * 32 + lane];
                float4 pv = p4[(size_t)c * 32 + lane];
                ax.x += w * xv.x; ax.y += w * xv.y; ax.z += w * xv.z; ax.w += w * xv.w;
                ap.x += w * pv.x; ap.y += w * pv.y; ap.z += w * pv.z; ap.w += w * pv.w;
            }
        }
        int pos = lr * BLD + lane * 4;
        split_store(sm, SM_AXH, SM_AXL, pos,     ax.x);
        split_store(sm, SM_AXH, SM_AXL, pos + 1, ax.y);
        split_store(sm, SM_AXH, SM_AXL, pos + 2, ax.z);
        split_store(sm, SM_AXH, SM_AXL, pos + 3, ax.w);
        split_store(sm, SM_AYH, SM_AYL, pos,     ax.x + ap.x);
        split_store(sm, SM_AYH, SM_AYL, pos + 1, ax.y + ap.y);
        split_store(sm, SM_AYH, SM_AYL, pos + 2, ax.z + ap.z);
        split_store(sm, SM_AYH, SM_AYL, pos + 3, ax.w + ap.w);
    }
    stage_B(sm, W_on, t);
    __syncthreads();

    FragC acc[2][2];
    // ---- S @ W_on -> embed product ----
    mm_block(sm, SM_AYH, acc, wid);
    store_prod_g(acc, g_TMP + (size_t)row0 * 128, 128, wid);
    __syncthreads();                            // product visible; B free
    // embed epilogue: out = x + perb + S@W_on + b_on
    #pragma unroll
    for (int i = 0; i < 8; i++) {
        int idx = t + i * 512;
        int r = idx >> 5, c4 = idx & 31;
        int gr = row0 + r;
        if (gr < NN) {
            float4 xv = x4[(size_t)gr * 32 + c4];
            float4 pv = p4[(size_t)gr * 32 + c4];
            float4 pr = ((const float4*)g_TMP)[(size_t)gr * 32 + c4];
            float4 bv = ((const float4*)b_on)[c4];
            ((float4*)out)[(size_t)gr * 32 + c4] =
                make_float4(xv.x + pv.x + pr.x + bv.x, xv.y + pv.y + pr.y + bv.y,
                            xv.z + pv.z + pr.z + bv.z, xv.w + pv.w + pr.w + bv.w);
        }
    }
    // ---- targets: B = W_tg ----
    stage_B(sm, W_tg, t);
    __syncthreads();
    mm_block(sm, SM_AYH, acc, wid);             // target_x = S @ W_tg (sec 0)
    store_prod_g(acc, g_AGG + (size_t)row0 * 256, 256, wid);
    mm_block(sm, SM_AXH, acc, wid);             // target_y = aggx @ W_tg (sec 1)
    store_prod_g(acc, g_AGG + (size_t)row0 * 256 + 128, 256, wid);
    __syncthreads();                            // done with B
    // ---- P1: B = W_on1 ----
    stage_B(sm, g_Won1, t);
    __syncthreads();
    mm_block(sm, SM_AXH, acc, wid);             // P1 sec0 = aggx @ W_on1
    __syncthreads();                            // AX images dead
    store_prod_s(acc, fs0, wid);
    mm_block(sm, SM_AYH, acc, wid);             // P1 sec1 = S @ W_on1
    __syncthreads();                            // AY images dead
    store_prod_s(acc, fs1, wid);
    __syncthreads();
    // write P1 (+c1) and BN stats
    #pragma unroll
    for (int i = 0; i < 64; i++) {
        int idx = t + i * 512;                  // 0..32767
        int sec = idx >> 14, rem = idx & 16383;
        int r = rem >> 7, c = rem & 127;
        float* fs = sec ? fs1 : fs0;
        float v = fs[r * SLD + c] + g_c1[c];
        fs[r * SLD + c] = v;
        g_P1[((size_t)row0 + r) * 256 + sec * 128 + c] = v;
    }
    __syncthreads();
    if (t < 256) {
        int sec = t >> 7, col = t & 127;
        const float* fs = sec ? fs1 : fs0;
        float s = 0.f, q = 0.f;
        int rmax = NN - row0; if (rmax > 128) rmax = 128;
        for (int r = 0; r < rmax; r++) {
            float v = fs[r * SLD + col];
            s += v; q += v * v;
        }
        atomicAdd(&g_bnsum[sec * 128 + col], s);
        atomicAdd(&g_bnsum[256 + sec * 128 + col], q);
    }
}

__global__ void k_bn_final(const float* __restrict__ bn_g, const float* __restrict__ bn_b) {
    int t = threadIdx.x;  // 0..255
    float inv_n = 1.f / (float)NN;
    float mean = g_bnsum[t] * inv_n;
    float var = g_bnsum[256 + t] * inv_n - mean * mean;
    int f = t & 127;
    float sc = bn_g[f] * rsqrtf(var + 1e-5f);
    g_bnaff[t] = sc;
    g_bnaff[256 + t] = bn_b[f] - mean * sc;
}

// ---------------- pred stage 2 (both secs) + cosine loss ----------------
__global__ __launch_bounds__(512, 1) void k_mm_p2(const float* __restrict__ b_tg,
                                                  const float* __restrict__ prelu_a,
                                                  const float* __restrict__ W2,
                                                  const float* __restrict__ b2) {
    extern __shared__ __nv_bfloat16 sm[];
    float* fs0 = (float*)sm;
    float* fs1 = (float*)((char*)sm + SM_AYH * 2);
    __shared__ float warp_l[16];
    int t = threadIdx.x, wid = t >> 5, lane = t & 31;
    int row0 = blockIdx.x * 128;
    float alpha = prelu_a[0];
    #pragma unroll
    for (int i = 0; i < 32; i++) {
        int idx = t + i * 512;
        int r = idx >> 7, c = idx & 127;
        int gr = row0 + r;
        float vx = 0.f, vy = 0.f;
        if (gr < NN) {
            float hx = g_P1[(size_t)gr * 256 + c];
            float hy = g_P1[(size_t)gr * 256 + 128 + c];
            vx = hx * g_bnaff[c] + g_bnaff[256 + c];
            vy = hy * g_bnaff[128 + c] + g_bnaff[384 + c];
            vx = vx > 0.f ? vx : alpha * vx;
            vy = vy > 0.f ? vy : alpha * vy;
        }
        split_store(sm, SM_AXH, SM_AXL, r * BLD + c, vx);
        split_store(sm, SM_AYH, SM_AYL, r * BLD + c, vy);
    }
    stage_B(sm, W2, t);
    __syncthreads();
    FragC acc[2][2];
    mm_block(sm, SM_AXH, acc, wid);            // px
    __syncthreads();
    store_prod_s(acc, fs0, wid);
    mm_block(sm, SM_AYH, acc, wid);            // py
    __syncthreads();
    store_prod_s(acc, fs1, wid);
    __syncthreads();

    float4 bb = *(const float4*)(b2 + lane * 4);
    float4 bt = *(const float4*)(b_tg + lane * 4);
    float lsum = 0.f;
    for (int j = 0; j < 16; j++) {
        int job = wid * 16 + j;                // 0..255
        int sec = job >> 7, r = job & 127;
        int gr = row0 + r;
        if (gr < NN) {
            const float* fs = sec ? fs1 : fs0;
            float p0 = fs[r * SLD + lane * 4]     + bb.x;
            float p1 = fs[r * SLD + lane * 4 + 1] + bb.y;
            float p2 = fs[r * SLD + lane * 4 + 2] + bb.z;
            float p3 = fs[r * SLD + lane * 4 + 3] + bb.w;
            float4 tg = *(const float4*)(g_AGG + (size_t)gr * 256 + sec * 128 + lane * 4);
            tg.x += bt.x; tg.y += bt.y; tg.z += bt.z; tg.w += bt.w;
            float dot = p0 * tg.x + p1 * tg.y + p2 * tg.z + p3 * tg.w;
            float np  = p0 * p0 + p1 * p1 + p2 * p2 + p3 * p3;
            float nt  = tg.x * tg.x + tg.y * tg.y + tg.z * tg.z + tg.w * tg.w;
            #pragma unroll
            for (int s = 16; s; s >>= 1) {
                dot += __shfl_xor_sync(0xFFFFFFFFu, dot, s);
                np  += __shfl_xor_sync(0xFFFFFFFFu, np, s);
                nt  += __shfl_xor_sync(0xFFFFFFFFu, nt, s);
            }
            if (lane == 0) {
                float d1 = fmaxf(sqrtf(np), 1e-12f);
                float d2 = fmaxf(sqrtf(nt), 1e-12f);
                lsum += 2.f - 2.f * dot / (d1 * d2);
            }
        }
    }
    if (lane == 0) warp_l[wid] = lsum;
    __syncthreads();
    if (t == 0) {
        float s = 0.f;
        #pragma unroll
        for (int w = 0; w < 16; w++) s += warp_l[w];
        atomicAdd(&g_loss, s);
    }
}

__global__ void k_final(float* out, int out_size) {
    out[out_size - 1] = g_loss * (1.f / (float)NN);
}

// ---------------- host ----------------
extern "C" void kernel_launch(void* const* d_in, const int* in_sizes, int n_in,
                              void* d_out, int out_size) {
    const float* x       = (const float*)d_in[0];
    const float* perb    = (const float*)d_in[1];
    const int*   erow    = (const int*)d_in[2];
    const int*   ecol    = (const int*)d_in[3];
    const float* ew      = (const float*)d_in[4];
    const float* W_on    = (const float*)d_in[5];
    const float* b_on    = (const float*)d_in[6];
    const float* W_tg    = (const float*)d_in[7];
    const float* b_tg    = (const float*)d_in[8];
    const float* W1      = (const float*)d_in[9];
    const float* b1      = (const float*)d_in[10];
    const float* bn_g    = (const float*)d_in[11];
    const float* bn_b    = (const float*)d_in[12];
    const float* prelu_a = (const float*)d_in[13];
    const float* W2      = (const float*)d_in[14];
    const float* b2      = (const float*)d_in[15];
    float* out = (float*)d_out;

    cudaFuncSetAttribute(k_mega, cudaFuncAttributeMaxDynamicSharedMemorySize, DYN_SMEM);
    cudaFuncSetAttribute(k_mm_p2, cudaFuncAttributeMaxDynamicSharedMemorySize, DYN_SMEM);

    k_zero<<<196, 256>>>();
    k_hist<<<3125, 256>>>(erow);
    k_c1<<<1, 128>>>(b_on, W1, b1);
    k_won1<<<64, 256>>>(W_on, W1);
    k_scan1<<<49, 1024>>>();
    k_scan2<<<1, 32>>>();
    k_scan3<<<49, 1024>>>();
    k_scatter<<<3125, 256>>>(erow, ecol, ew);
    k_mega<<<391, 512, DYN_SMEM>>>(x, perb, b_on, W_on, W_tg, out);
    k_bn_final<<<1, 256>>>(bn_g, bn_b);
    k_mm_p2<<<391, 512, DYN_SMEM>>>(b_tg, prelu_a, W2, b2);
    k_final<<<1, 1>>>(out, out_size);
}